// round 15
// baseline (speedup 1.0000x reference)
#include <cuda_runtime.h>
#include <cuda_fp16.h>

#define Tn   8192
#define Hn   1024
#define FUT  16
#define NCTA 128
#define TPB  256

// dynamic smem byte offsets (weights live in registers; smem is tiny)
#define OFF_H0   0        // half[1024]
#define OFF_H1   2048     // half[1024]
#define OFF_WX   4096     // float[32][16]
#define OFF_B0   6144
#define OFF_B1   6272
#define OFF_X    6400
#define SMEM_SZ  6464

__device__ float g_hist[(Tn + FUT + 2) * Hn]; // fp32 h1(t) at row t+1 (for MLP)
__device__ float g_mlpA[Tn * Hn];
__device__ float g_mlpB[Tn * Hn];
__device__ __align__(16) __half g_h0h[2][Hn];   // legacy (future rollout only)
__device__ __align__(16) __half g_h1h[2][Hn];
__device__ float g_vec[2][Hn];
__device__ float g_xfut[16];
__device__ float g_sink;
__device__ unsigned g_flags[NCTA * 32];   // MLP/future-phase barrier flags (128B stride)
// fused sync+data line: words 0..3 = h0[8] halves, 4..7 = h1[8] halves, 8 = flag
__device__ __align__(128) unsigned g_line[2][NCTA][32];
__device__ unsigned g_runbase;            // +16384 per launch (replay-safe epochs)

__device__ __forceinline__ float sigf(float x) { return 1.0f / (1.0f + __expf(-x)); }
__device__ __forceinline__ float leaky(float x) { return x >= 0.0f ? x : 0.8f * x; }
__device__ __forceinline__ float tanhfast(float x) {
    float r; asm("tanh.approx.f32 %0, %1;" : "=f"(r) : "f"(x)); return r;
}

// generic flat grid barrier (R11 winner) — used by MLP/future phases only
__device__ __forceinline__ void gridbar(unsigned &epoch, int tid, int cta) {
    epoch++;
    __syncthreads();
    if (tid == 0) {
        __threadfence();
        *(volatile unsigned *)&g_flags[cta << 5] = epoch;
    }
    if (tid < NCTA) {
        const volatile unsigned *fp = &g_flags[tid << 5];
        while (*fp < epoch) {
            float a = 1.0f;
#pragma unroll
            for (int i = 0; i < 16; ++i)
                asm volatile("fma.rn.f32 %0, %0, %1, 0f00000000;" : "+f"(a) : "f"(1.000001f));
            if (a == 0.0f) g_sink = a;
        }
        __threadfence();
    }
    __syncthreads();
}

// register-resident fp16 dot: weights wreg[BASE..BASE+15] (uint4 of half2),
// vector from smem (broadcast). BASE must be a literal for constant indexing.
#define DOTREG(BASE, V, OUT) do {                                              \
    const uint4 *vp_ = reinterpret_cast<const uint4 *>(V);                     \
    __half2 q0_ = __float2half2_rn(0.f), q1_ = q0_, q2_ = q0_, q3_ = q0_;      \
    _Pragma("unroll")                                                          \
    for (int i_ = 0; i_ < 16; ++i_) {                                          \
        uint4 wv_ = wreg[(BASE) + i_];                                         \
        uint4 vv_ = vp_[sub + (i_ << 3)];                                      \
        q0_ = __hfma2(*(__half2 *)&wv_.x, *(__half2 *)&vv_.x, q0_);            \
        q1_ = __hfma2(*(__half2 *)&wv_.y, *(__half2 *)&vv_.y, q1_);            \
        q2_ = __hfma2(*(__half2 *)&wv_.z, *(__half2 *)&vv_.z, q2_);            \
        q3_ = __hfma2(*(__half2 *)&wv_.w, *(__half2 *)&vv_.w, q3_);            \
    }                                                                          \
    q0_ = __hadd2(q0_, q1_);                                                   \
    q2_ = __hadd2(q2_, q3_);                                                   \
    float2 f0_ = __half22float2(q0_), f2_ = __half22float2(q2_);               \
    OUT = (f0_.x + f0_.y) + (f2_.x + f2_.y);                                   \
} while (0)

__device__ __forceinline__ float red8(float a) {
    a += __shfl_xor_sync(0xffffffffu, a, 1);
    a += __shfl_xor_sync(0xffffffffu, a, 2);
    a += __shfl_xor_sync(0xffffffffu, a, 4);
    return a;
}

__global__ void noop_kernel() {}

__global__ void __launch_bounds__(TPB, 1) scan_kernel(
    const float *__restrict__ x,
    const float *__restrict__ Wih0, const float *__restrict__ Whh0,
    const float *__restrict__ bih0, const float *__restrict__ bhh0,
    const float *__restrict__ Wih1, const float *__restrict__ Whh1,
    const float *__restrict__ bih1, const float *__restrict__ bhh1,
    const float *__restrict__ linW, const float *__restrict__ linb,
    const float *__restrict__ W1, const float *__restrict__ b1,
    const float *__restrict__ W2, const float *__restrict__ b2,
    const float *__restrict__ Wo, const float *__restrict__ bo,
    float *__restrict__ outp)
{
    extern __shared__ char smraw[];
    __half *H0s = (__half *)(smraw + OFF_H0);
    __half *H1s = (__half *)(smraw + OFF_H1);
    float *WXs = (float *)(smraw + OFF_WX);
    float *B0s = (float *)(smraw + OFF_B0);
    float *B1s = (float *)(smraw + OFF_B1);
    float *Xs  = (float *)(smraw + OFF_X);

    const int tid = threadIdx.x;
    const int cta = blockIdx.x;
    const int r = tid >> 3, sub = tid & 7;   // r = unit_local*4 + gate
    const int w = tid >> 5, lane = tid & 31; // warp w <-> unit w

    const unsigned base = __ldcg(&g_runbase);   // per-launch epoch base

    // ---- load weights into REGISTERS (fp16 packed), one-time ----
    uint4 wreg[48];
    {
        const int grow = ((r & 3) << 10) + (cta << 3) + (r >> 2); // gate*1024+cta*8+unit
#pragma unroll
        for (int d = 0; d < 3; ++d) {
            const float *src = (d == 0) ? Whh0 : (d == 1) ? Wih1 : Whh1;
            const float4 *rowp = reinterpret_cast<const float4 *>(src + grow * 1024);
#pragma unroll
            for (int i = 0; i < 16; ++i) {
                float4 f0 = rowp[(sub + (i << 3)) * 2];
                float4 f1 = rowp[(sub + (i << 3)) * 2 + 1];
                __half2 h0 = __floats2half2_rn(f0.x, f0.y);
                __half2 h1 = __floats2half2_rn(f0.z, f0.w);
                __half2 h2 = __floats2half2_rn(f1.x, f1.y);
                __half2 h3 = __floats2half2_rn(f1.z, f1.w);
                wreg[d * 16 + i] = make_uint4(*(unsigned *)&h0, *(unsigned *)&h1,
                                              *(unsigned *)&h2, *(unsigned *)&h3);
            }
        }
    }
    if (tid < 32) {
        int grow = ((tid & 3) << 10) + (cta << 3) + (tid >> 2);
        B0s[tid] = bih0[grow] + bhh0[grow];
        B1s[tid] = bih1[grow] + bhh1[grow];
        for (int k = 0; k < 16; ++k)
            WXs[tid * 16 + k] = (k < 15) ? Wih0[grow * 15 + k] : 0.f;
    }
    __syncthreads();

    unsigned epoch = *(volatile unsigned *)&g_flags[cta << 5];  // MLP-phase base
    float c0r = 0.f, c1r = 0.f;

    // ---- skewed scan with FUSED barrier+staging ----
    // line[p=s&1][cta] written at superstep s: h0(s), h1(s-1), flag=base+s+1
    // reader at superstep s polls line[(s+1)&1][*] for flag>=base+s, then pulls
    // the h data from the SAME line into smem (one L2 transaction per peer).
    for (int s = 0; s <= Tn; ++s) {
        if (s >= 1 && tid < NCTA) {
            const int parR = (s + 1) & 1;
            const volatile unsigned *fp = &g_line[parR][tid][8];
            const unsigned need = base + (unsigned)s;
            while (*fp < need) {
                float a = 1.0f;
#pragma unroll
                for (int i = 0; i < 16; ++i)
                    asm volatile("fma.rn.f32 %0, %0, %1, 0f00000000;" : "+f"(a) : "f"(1.000001f));
                if (a == 0.0f) g_sink = a;
            }
            uint4 va = __ldcg((const uint4 *)&g_line[parR][tid][0]);
            uint4 vb = __ldcg((const uint4 *)&g_line[parR][tid][4]);
            reinterpret_cast<uint4 *>(H0s)[tid] = va;
            reinterpret_cast<uint4 *>(H1s)[tid] = vb;
        }
        if (tid < 15 && s < Tn) Xs[tid] = x[s * 15 + tid];
        __syncthreads();

        float a0 = 0.f, a1 = 0.f;
        if (s > 0 && s < Tn) DOTREG(0, H0s, a0);
        if (s >= 1) {
            DOTREG(16, H0s, a1);
            if (s >= 2) { float t1; DOTREG(32, H1s, t1); a1 += t1; }
        }
        a0 = red8(a0);
        a1 = red8(a1);
        if (sub == 0) {
            float xi = 0.f;
#pragma unroll
            for (int k2 = 0; k2 < 15; ++k2) xi = fmaf(WXs[r * 16 + k2], Xs[k2], xi);
            a0 += xi + B0s[r];
            a1 += B1s[r];
        }
        float i0 = __shfl_sync(0xffffffffu, a0, 0),  f0 = __shfl_sync(0xffffffffu, a0, 8);
        float gg0 = __shfl_sync(0xffffffffu, a0, 16), o0 = __shfl_sync(0xffffffffu, a0, 24);
        float i1 = __shfl_sync(0xffffffffu, a1, 0),  f1 = __shfl_sync(0xffffffffu, a1, 8);
        float gg1 = __shfl_sync(0xffffffffu, a1, 16), o1 = __shfl_sync(0xffffffffu, a1, 24);
        if (lane == 0) {
            const int parW = s & 1;
            __half *lp = (__half *)&g_line[parW][cta][0];
            if (s < Tn) {
                c0r = sigf(f0) * c0r + sigf(i0) * tanhfast(gg0);
                __half h0h = __float2half_rn(sigf(o0) * tanhfast(c0r));
                lp[w] = h0h;
                if (s == Tn - 1) g_h0h[1][(cta << 3) + w] = h0h;  // seed rollout
            }
            if (s >= 1) {
                c1r = sigf(f1) * c1r + sigf(i1) * tanhfast(gg1);
                float h = sigf(o1) * tanhfast(c1r);
                __half h1h = __float2half_rn(h);
                lp[8 + w] = h1h;
                g_hist[s * Hn + (cta << 3) + w] = h;
                if (s == Tn) g_h1h[1][(cta << 3) + w] = h1h;      // seed rollout
            }
        }
        __syncthreads();
        if (tid == 0) {
            __threadfence();   // release: line data visible before flag
            *(volatile unsigned *)&g_line[s & 1][cta][8] = base + (unsigned)s + 1;
        }
    }

    // ---- in-kernel MLP helpers (grid-wide matvec, weights from L2) ----
    auto matvec = [&](const float *W, const float *b, const float *vin, float *vout) {
        int j = (cta << 3) + w;
        const float4 *wp = reinterpret_cast<const float4 *>(W + (j << 10));
        const float4 *vp = reinterpret_cast<const float4 *>(vin);
        float q0 = 0.f, q1 = 0.f, q2 = 0.f, q3 = 0.f;
#pragma unroll
        for (int i = 0; i < 8; ++i) {
            float4 a = wp[lane + (i << 5)];
            float4 v = __ldcg(vp + lane + (i << 5));
            q0 = fmaf(a.x, v.x, q0); q1 = fmaf(a.y, v.y, q1);
            q2 = fmaf(a.z, v.z, q2); q3 = fmaf(a.w, v.w, q3);
        }
        float acc = (q0 + q1) + (q2 + q3);
#pragma unroll
        for (int o = 16; o > 0; o >>= 1) acc += __shfl_xor_sync(0xffffffffu, acc, o);
        if (lane == 0) vout[j] = leaky(acc + b[j]);
    };
    auto wo_out = [&](const float *vin, int outrow) {
        if (cta < 15 && tid < 32) {
            const float4 *wp = reinterpret_cast<const float4 *>(Wo + (cta << 10));
            const float4 *vp = reinterpret_cast<const float4 *>(vin);
            float acc = 0.f;
#pragma unroll
            for (int i = 0; i < 8; ++i) {
                float4 a = wp[tid + (i << 5)];
                float4 v = __ldcg(vp + tid + (i << 5));
                acc += a.x * v.x + a.y * v.y + a.z * v.z + a.w * v.w;
            }
#pragma unroll
            for (int o = 16; o > 0; o >>= 1) acc += __shfl_xor_sync(0xffffffffu, acc, o);
            if (tid == 0) {
                float rv = leaky(acc + bo[cta]);
                g_xfut[cta] = rv;
                if (outrow >= 0) outp[outrow * 15 + cta] = rv;
            }
        }
    };
    auto mlp_chain = [&](const float *vin, int outrow) {
        matvec(linW,           linb,      vin,      g_vec[0]); gridbar(epoch, tid, cta);
        matvec(linW + Hn * Hn, linb + Hn, g_vec[0], g_vec[1]); gridbar(epoch, tid, cta);
        matvec(W1,             b1,        g_vec[1], g_vec[0]); gridbar(epoch, tid, cta);
        matvec(W2,             b2,        g_vec[0], g_vec[1]); gridbar(epoch, tid, cta);
        wo_out(g_vec[1], outrow);                               gridbar(epoch, tid, cta);
    };

    // last = mlp(h1(T-1))
    mlp_chain(&g_hist[Tn * Hn], -1);

    // ---- future rollout (legacy arrays + generic barrier) ----
    for (int kf = 0; kf < FUT; ++kf) {
        {   // layer0
            const unsigned *h0src = (const unsigned *)g_h0h[(kf + 1) & 1];
            unsigned *d0 = (unsigned *)H0s;
#pragma unroll
            for (int i = 0; i < 2; ++i) d0[tid + (i << 8)] = __ldcg(h0src + tid + (i << 8));
            if (tid < 15) Xs[tid] = __ldcg(&g_xfut[tid]);
            __syncthreads();
            float a0; DOTREG(0, H0s, a0);
            a0 = red8(a0);
            if (sub == 0) {
                float xi = 0.f;
#pragma unroll
                for (int k2 = 0; k2 < 15; ++k2) xi = fmaf(WXs[r * 16 + k2], Xs[k2], xi);
                a0 += xi + B0s[r];
            }
            float i0 = __shfl_sync(0xffffffffu, a0, 0),  f0 = __shfl_sync(0xffffffffu, a0, 8);
            float gg0 = __shfl_sync(0xffffffffu, a0, 16), o0 = __shfl_sync(0xffffffffu, a0, 24);
            if (lane == 0) {
                c0r = sigf(f0) * c0r + sigf(i0) * tanhfast(gg0);
                g_h0h[kf & 1][(cta << 3) + w] = __float2half_rn(sigf(o0) * tanhfast(c0r));
            }
            gridbar(epoch, tid, cta);
        }
        {   // layer1
            const unsigned *h0src = (const unsigned *)g_h0h[kf & 1];
            const unsigned *h1src = (const unsigned *)g_h1h[(kf + 1) & 1];
            unsigned *d0 = (unsigned *)H0s, *d1 = (unsigned *)H1s;
#pragma unroll
            for (int i = 0; i < 2; ++i) {
                d0[tid + (i << 8)] = __ldcg(h0src + tid + (i << 8));
                d1[tid + (i << 8)] = __ldcg(h1src + tid + (i << 8));
            }
            __syncthreads();
            float a1, t1;
            DOTREG(16, H0s, a1);
            DOTREG(32, H1s, t1);
            a1 = red8(a1 + t1);
            if (sub == 0) a1 += B1s[r];
            float i1 = __shfl_sync(0xffffffffu, a1, 0),  f1 = __shfl_sync(0xffffffffu, a1, 8);
            float gg1 = __shfl_sync(0xffffffffu, a1, 16), o1 = __shfl_sync(0xffffffffu, a1, 24);
            if (lane == 0) {
                c1r = sigf(f1) * c1r + sigf(i1) * tanhfast(gg1);
                float h = sigf(o1) * tanhfast(c1r);
                g_h1h[kf & 1][(cta << 3) + w] = __float2half_rn(h);
                g_hist[(Tn + kf + 1) * Hn + (cta << 3) + w] = h;
            }
            gridbar(epoch, tid, cta);
        }
        mlp_chain(&g_hist[(Tn + kf + 1) * Hn], Tn + kf);
    }

    // bump per-launch epoch base (after final gridbar; all CTAs read base at entry)
    if (cta == 0 && tid == 0)
        *(volatile unsigned *)&g_runbase = base + 16384u;
}

// ---- batched MLP GEMM: C[8192,1024] = leaky(A @ W^T + b) ----
__global__ void __launch_bounds__(256) gemm_leaky_kernel(
    const float *__restrict__ W, const float *__restrict__ bias, int stage)
{
    const float *A = (stage == 0) ? (g_hist + Hn) : ((stage & 1) ? g_mlpA : g_mlpB);
    float *C = (stage & 1) ? g_mlpB : g_mlpA;

    __shared__ float As[16][68];
    __shared__ float Ws[16][68];
    int tid = threadIdx.x;
    int m0 = blockIdx.y << 6, n0 = blockIdx.x << 6;
    int lr = tid >> 2;
    int lk = (tid & 3) << 2;
    int tx = tid & 15, ty = tid >> 4;
    float acc[4][4] = {};

    for (int k0 = 0; k0 < 1024; k0 += 16) {
        float4 av = *reinterpret_cast<const float4 *>(&A[(m0 + lr) * 1024 + k0 + lk]);
        float4 wv = *reinterpret_cast<const float4 *>(&W[(n0 + lr) * 1024 + k0 + lk]);
        __syncthreads();
        As[lk + 0][lr] = av.x; As[lk + 1][lr] = av.y; As[lk + 2][lr] = av.z; As[lk + 3][lr] = av.w;
        Ws[lk + 0][lr] = wv.x; Ws[lk + 1][lr] = wv.y; Ws[lk + 2][lr] = wv.z; Ws[lk + 3][lr] = wv.w;
        __syncthreads();
#pragma unroll
        for (int k = 0; k < 16; ++k) {
            float4 a = *reinterpret_cast<const float4 *>(&As[k][ty << 2]);
            float4 b = *reinterpret_cast<const float4 *>(&Ws[k][tx << 2]);
            acc[0][0] = fmaf(a.x, b.x, acc[0][0]); acc[0][1] = fmaf(a.x, b.y, acc[0][1]);
            acc[0][2] = fmaf(a.x, b.z, acc[0][2]); acc[0][3] = fmaf(a.x, b.w, acc[0][3]);
            acc[1][0] = fmaf(a.y, b.x, acc[1][0]); acc[1][1] = fmaf(a.y, b.y, acc[1][1]);
            acc[1][2] = fmaf(a.y, b.z, acc[1][2]); acc[1][3] = fmaf(a.y, b.w, acc[1][3]);
            acc[2][0] = fmaf(a.z, b.x, acc[2][0]); acc[2][1] = fmaf(a.z, b.y, acc[2][1]);
            acc[2][2] = fmaf(a.z, b.z, acc[2][2]); acc[2][3] = fmaf(a.z, b.w, acc[2][3]);
            acc[3][0] = fmaf(a.w, b.x, acc[3][0]); acc[3][1] = fmaf(a.w, b.y, acc[3][1]);
            acc[3][2] = fmaf(a.w, b.z, acc[3][2]); acc[3][3] = fmaf(a.w, b.w, acc[3][3]);
        }
    }
    float4 bb = *reinterpret_cast<const float4 *>(&bias[n0 + (tx << 2)]);
#pragma unroll
    for (int i = 0; i < 4; ++i) {
        int row = m0 + (ty << 2) + i;
        float4 o;
        o.x = leaky(acc[i][0] + bb.x);
        o.y = leaky(acc[i][1] + bb.y);
        o.z = leaky(acc[i][2] + bb.z);
        o.w = leaky(acc[i][3] + bb.w);
        *reinterpret_cast<float4 *>(&C[row * 1024 + n0 + (tx << 2)]) = o;
    }
}

__global__ void __launch_bounds__(512) wo_kernel(
    const float *__restrict__ Wo, const float *__restrict__ bo, float *__restrict__ out)
{
    int t = blockIdx.x;
    int w = threadIdx.x >> 5, l = threadIdx.x & 31;
    if (w >= 15) return;
    const float4 *ap = reinterpret_cast<const float4 *>(g_mlpB + t * Hn);
    const float4 *wp = reinterpret_cast<const float4 *>(Wo + (w << 10));
    float acc = 0.f;
#pragma unroll
    for (int i = 0; i < 8; ++i) {
        float4 a = ap[l + (i << 5)];
        float4 ww = wp[l + (i << 5)];
        acc += a.x * ww.x + a.y * ww.y + a.z * ww.z + a.w * ww.w;
    }
#pragma unroll
    for (int o = 16; o > 0; o >>= 1) acc += __shfl_xor_sync(0xffffffffu, acc, o);
    if (l == 0) out[t * 15 + w] = leaky(acc + bo[w]);
}

extern "C" void kernel_launch(void* const* d_in, const int* in_sizes, int n_in,
                              void* d_out, int out_size) {
    const float *x    = (const float *)d_in[0];
    const float *Wih0 = (const float *)d_in[1];
    const float *Whh0 = (const float *)d_in[2];
    const float *bih0 = (const float *)d_in[3];
    const float *bhh0 = (const float *)d_in[4];
    const float *Wih1 = (const float *)d_in[5];
    const float *Whh1 = (const float *)d_in[6];
    const float *bih1 = (const float *)d_in[7];
    const float *bhh1 = (const float *)d_in[8];
    const float *linW = (const float *)d_in[9];
    const float *linb = (const float *)d_in[10];
    const float *W1   = (const float *)d_in[11];
    const float *b1   = (const float *)d_in[12];
    const float *W2   = (const float *)d_in[13];
    const float *b2   = (const float *)d_in[14];
    const float *Wo   = (const float *)d_in[15];
    const float *bo   = (const float *)d_in[16];
    float *outp = (float *)d_out;

    cudaFuncSetAttribute(scan_kernel, cudaFuncAttributeMaxDynamicSharedMemorySize, SMEM_SZ);

    noop_kernel<<<1, 32>>>();
    noop_kernel<<<1, 32>>>();
    scan_kernel<<<NCTA, TPB, SMEM_SZ>>>(x, Wih0, Whh0, bih0, bhh0,
                                        Wih1, Whh1, bih1, bhh1,
                                        linW, linb, W1, b1, W2, b2, Wo, bo, outp);
    dim3 gg(16, 128);
    gemm_leaky_kernel<<<gg, 256>>>(linW,          linb,       0);
    gemm_leaky_kernel<<<gg, 256>>>(linW + Hn*Hn,  linb + Hn,  1);
    gemm_leaky_kernel<<<gg, 256>>>(W1,            b1,         2);
    gemm_leaky_kernel<<<gg, 256>>>(W2,            b2,         3);
    wo_kernel<<<Tn, 512>>>(Wo, bo, outp);
}

// round 16
// speedup vs baseline: 1.1656x; 1.1656x over previous
#include <cuda_runtime.h>
#include <cuda_fp16.h>

#define Tn   8192
#define Hn   1024
#define FUT  16
#define NCTA 128
#define TPB  256

// dynamic smem byte offsets (weights live in registers; smem is tiny)
#define OFF_H0   0        // half[1024]
#define OFF_H1   2048     // half[1024]
#define OFF_WX   4096     // float[32][16]
#define OFF_B0   6144
#define OFF_B1   6272
#define OFF_X    6400
#define SMEM_SZ  6464

__device__ float g_hist[(Tn + FUT + 2) * Hn]; // fp32 h1(t) at row t+1 (for MLP)
__device__ float g_mlpA[Tn * Hn];
__device__ float g_mlpB[Tn * Hn];
__device__ __align__(16) __half g_h0h[2][Hn];
__device__ __align__(16) __half g_h1h[2][Hn];
__device__ float g_vec[2][Hn];
__device__ float g_xfut[16];
__device__ float g_sink;
__device__ unsigned g_flags[NCTA * 32];   // 128B stride: one L2 line per flag

__device__ __forceinline__ float sigf(float x) { return 1.0f / (1.0f + __expf(-x)); }
__device__ __forceinline__ float leaky(float x) { return x >= 0.0f ? x : 0.8f * x; }
__device__ __forceinline__ float tanhfast(float x) {
    float r; asm("tanh.approx.f32 %0, %1;" : "=f"(r) : "f"(x)); return r;
}

// flat grid barrier (R11/R14 winner): volatile flags at 128B stride, 128
// parallel pollers per CTA, short (~64cyc) dependent-FFMA backoff.
__device__ __forceinline__ void gridbar(unsigned &epoch, int tid, int cta) {
    epoch++;
    __syncthreads();                       // all block work (incl. global h stores) done
    if (tid == 0) {
        __threadfence();                   // release: h stores visible before flag
        *(volatile unsigned *)&g_flags[cta << 5] = epoch;
    }
    if (tid < NCTA) {
        const volatile unsigned *fp = &g_flags[tid << 5];
        while (*fp < epoch) {
            float a = 1.0f;
#pragma unroll
            for (int i = 0; i < 16; ++i)
                asm volatile("fma.rn.f32 %0, %0, %1, 0f00000000;" : "+f"(a) : "f"(1.000001f));
            if (a == 0.0f) g_sink = a;     // never true; keeps backoff chain live
        }
        __threadfence();                   // acquire
    }
    __syncthreads();
}

// register-resident fp16 dot: weights wreg[BASE..BASE+15] (uint4 of half2),
// vector from smem (broadcast). BASE must be a literal for constant indexing.
#define DOTREG(BASE, V, OUT) do {                                              \
    const uint4 *vp_ = reinterpret_cast<const uint4 *>(V);                     \
    __half2 q0_ = __float2half2_rn(0.f), q1_ = q0_, q2_ = q0_, q3_ = q0_;      \
    _Pragma("unroll")                                                          \
    for (int i_ = 0; i_ < 16; ++i_) {                                          \
        uint4 wv_ = wreg[(BASE) + i_];                                         \
        uint4 vv_ = vp_[sub + (i_ << 3)];                                      \
        q0_ = __hfma2(*(__half2 *)&wv_.x, *(__half2 *)&vv_.x, q0_);            \
        q1_ = __hfma2(*(__half2 *)&wv_.y, *(__half2 *)&vv_.y, q1_);            \
        q2_ = __hfma2(*(__half2 *)&wv_.z, *(__half2 *)&vv_.z, q2_);            \
        q3_ = __hfma2(*(__half2 *)&wv_.w, *(__half2 *)&vv_.w, q3_);            \
    }                                                                          \
    q0_ = __hadd2(q0_, q1_);                                                   \
    q2_ = __hadd2(q2_, q3_);                                                   \
    float2 f0_ = __half22float2(q0_), f2_ = __half22float2(q2_);               \
    OUT = (f0_.x + f0_.y) + (f2_.x + f2_.y);                                   \
} while (0)

__device__ __forceinline__ float red8(float a) {
    a += __shfl_xor_sync(0xffffffffu, a, 1);
    a += __shfl_xor_sync(0xffffffffu, a, 2);
    a += __shfl_xor_sync(0xffffffffu, a, 4);
    return a;
}

__global__ void noop_kernel() {}

__global__ void __launch_bounds__(TPB, 1) scan_kernel(
    const float *__restrict__ x,
    const float *__restrict__ Wih0, const float *__restrict__ Whh0,
    const float *__restrict__ bih0, const float *__restrict__ bhh0,
    const float *__restrict__ Wih1, const float *__restrict__ Whh1,
    const float *__restrict__ bih1, const float *__restrict__ bhh1,
    const float *__restrict__ linW, const float *__restrict__ linb,
    const float *__restrict__ W1, const float *__restrict__ b1,
    const float *__restrict__ W2, const float *__restrict__ b2,
    const float *__restrict__ Wo, const float *__restrict__ bo,
    float *__restrict__ outp)
{
    extern __shared__ char smraw[];
    __half *H0s = (__half *)(smraw + OFF_H0);
    __half *H1s = (__half *)(smraw + OFF_H1);
    float *WXs = (float *)(smraw + OFF_WX);
    float *B0s = (float *)(smraw + OFF_B0);
    float *B1s = (float *)(smraw + OFF_B1);
    float *Xs  = (float *)(smraw + OFF_X);

    const int tid = threadIdx.x;
    const int cta = blockIdx.x;
    const int r = tid >> 3, sub = tid & 7;   // r = unit_local*4 + gate
    const int w = tid >> 5, lane = tid & 31; // warp w <-> unit w

    // ---- load weights into REGISTERS (fp16 packed), one-time ----
    // wreg[0..15]=Whh0 row, [16..31]=Wih1 row, [32..47]=Whh1 row
    uint4 wreg[48];
    {
        const int grow = ((r & 3) << 10) + (cta << 3) + (r >> 2); // gate*1024+cta*8+unit
#pragma unroll
        for (int d = 0; d < 3; ++d) {
            const float *src = (d == 0) ? Whh0 : (d == 1) ? Wih1 : Whh1;
            const float4 *rowp = reinterpret_cast<const float4 *>(src + grow * 1024);
#pragma unroll
            for (int i = 0; i < 16; ++i) {
                float4 f0 = rowp[(sub + (i << 3)) * 2];
                float4 f1 = rowp[(sub + (i << 3)) * 2 + 1];
                __half2 h0 = __floats2half2_rn(f0.x, f0.y);
                __half2 h1 = __floats2half2_rn(f0.z, f0.w);
                __half2 h2 = __floats2half2_rn(f1.x, f1.y);
                __half2 h3 = __floats2half2_rn(f1.z, f1.w);
                wreg[d * 16 + i] = make_uint4(*(unsigned *)&h0, *(unsigned *)&h1,
                                              *(unsigned *)&h2, *(unsigned *)&h3);
            }
        }
    }
    if (tid < 32) {
        int grow = ((tid & 3) << 10) + (cta << 3) + (tid >> 2);
        B0s[tid] = bih0[grow] + bhh0[grow];
        B1s[tid] = bih1[grow] + bhh1[grow];
        for (int k = 0; k < 16; ++k)
            WXs[tid * 16 + k] = (k < 15) ? Wih0[grow * 15 + k] : 0.f;
    }
    __syncthreads();

    // epoch base = this CTA's flag at entry (monotonic across launches)
    unsigned epoch = *(volatile unsigned *)&g_flags[cta << 5];
    float c0r = 0.f, c1r = 0.f;              // cell states live in lane 0 of each warp

    // x prefetch: xreg holds x(s) at loop-top of superstep s
    float xreg = (tid < 15) ? __ldcg(&x[tid]) : 0.f;

    // ---- skewed scan: superstep s does layer0(s) and layer1(s-1) ----
    for (int s = 0; s <= Tn; ++s) {
        {   // stage h vectors (half) into smem; cross-CTA data -> __ldcg
            const unsigned *h0src = (const unsigned *)g_h0h[(s + 1) & 1];
            const unsigned *h1src = (const unsigned *)g_h1h[s & 1];
            unsigned *d0 = (unsigned *)H0s, *d1 = (unsigned *)H1s;
#pragma unroll
            for (int i = 0; i < 2; ++i) {
                d0[tid + (i << 8)] = __ldcg(h0src + tid + (i << 8));
                d1[tid + (i << 8)] = __ldcg(h1src + tid + (i << 8));
            }
        }
        if (tid < 15 && s < Tn) Xs[tid] = xreg;
        __syncthreads();
        // prefetch next x; latency hides under dots + barrier
        if (tid < 15 && s + 1 < Tn) xreg = __ldcg(&x[(s + 1) * 15 + tid]);

        float a0 = 0.f, a1 = 0.f;
        if (s > 0 && s < Tn) DOTREG(0, H0s, a0);
        if (s >= 1) {
            DOTREG(16, H0s, a1);
            if (s >= 2) { float t1; DOTREG(32, H1s, t1); a1 += t1; }
        }
        a0 = red8(a0);
        a1 = red8(a1);
        if (sub == 0) {
            float xi = 0.f;
#pragma unroll
            for (int k2 = 0; k2 < 15; ++k2) xi = fmaf(WXs[r * 16 + k2], Xs[k2], xi);
            a0 += xi + B0s[r];
            a1 += B1s[r];
        }
        // gather gates i,f,g,o from lanes 0,8,16,24 to lane 0 of each warp
        float i0 = __shfl_sync(0xffffffffu, a0, 0),  f0 = __shfl_sync(0xffffffffu, a0, 8);
        float gg0 = __shfl_sync(0xffffffffu, a0, 16), o0 = __shfl_sync(0xffffffffu, a0, 24);
        float i1 = __shfl_sync(0xffffffffu, a1, 0),  f1 = __shfl_sync(0xffffffffu, a1, 8);
        float gg1 = __shfl_sync(0xffffffffu, a1, 16), o1 = __shfl_sync(0xffffffffu, a1, 24);
        if (lane == 0) {
            if (s < Tn) {
                c0r = sigf(f0) * c0r + sigf(i0) * tanhfast(gg0);
                g_h0h[s & 1][(cta << 3) + w] = __float2half_rn(sigf(o0) * tanhfast(c0r));
            }
            if (s >= 1) {
                c1r = sigf(f1) * c1r + sigf(i1) * tanhfast(gg1);
                float h = sigf(o1) * tanhfast(c1r);
                g_h1h[(s - 1) & 1][(cta << 3) + w] = __float2half_rn(h);
                g_hist[s * Hn + (cta << 3) + w] = h;
            }
        }
        gridbar(epoch, tid, cta);
    }

    // ---- in-kernel MLP helpers (grid-wide matvec, weights from L2) ----
    auto matvec = [&](const float *W, const float *b, const float *vin, float *vout) {
        int j = (cta << 3) + w;
        const float4 *wp = reinterpret_cast<const float4 *>(W + (j << 10));
        const float4 *vp = reinterpret_cast<const float4 *>(vin);
        float q0 = 0.f, q1 = 0.f, q2 = 0.f, q3 = 0.f;
#pragma unroll
        for (int i = 0; i < 8; ++i) {
            float4 a = wp[lane + (i << 5)];
            float4 v = __ldcg(vp + lane + (i << 5));
            q0 = fmaf(a.x, v.x, q0); q1 = fmaf(a.y, v.y, q1);
            q2 = fmaf(a.z, v.z, q2); q3 = fmaf(a.w, v.w, q3);
        }
        float acc = (q0 + q1) + (q2 + q3);
#pragma unroll
        for (int o = 16; o > 0; o >>= 1) acc += __shfl_xor_sync(0xffffffffu, acc, o);
        if (lane == 0) vout[j] = leaky(acc + b[j]);
    };
    auto wo_out = [&](const float *vin, int outrow) {
        if (cta < 15 && tid < 32) {
            const float4 *wp = reinterpret_cast<const float4 *>(Wo + (cta << 10));
            const float4 *vp = reinterpret_cast<const float4 *>(vin);
            float acc = 0.f;
#pragma unroll
            for (int i = 0; i < 8; ++i) {
                float4 a = wp[tid + (i << 5)];
                float4 v = __ldcg(vp + tid + (i << 5));
                acc += a.x * v.x + a.y * v.y + a.z * v.z + a.w * v.w;
            }
#pragma unroll
            for (int o = 16; o > 0; o >>= 1) acc += __shfl_xor_sync(0xffffffffu, acc, o);
            if (tid == 0) {
                float rv = leaky(acc + bo[cta]);
                g_xfut[cta] = rv;
                if (outrow >= 0) outp[outrow * 15 + cta] = rv;
            }
        }
    };
    auto mlp_chain = [&](const float *vin, int outrow) {
        matvec(linW,           linb,      vin,      g_vec[0]); gridbar(epoch, tid, cta);
        matvec(linW + Hn * Hn, linb + Hn, g_vec[0], g_vec[1]); gridbar(epoch, tid, cta);
        matvec(W1,             b1,        g_vec[1], g_vec[0]); gridbar(epoch, tid, cta);
        matvec(W2,             b2,        g_vec[0], g_vec[1]); gridbar(epoch, tid, cta);
        wo_out(g_vec[1], outrow);                               gridbar(epoch, tid, cta);
    };

    // last = mlp(h1(T-1))
    mlp_chain(&g_hist[Tn * Hn], -1);

    // ---- future rollout ----
    for (int kf = 0; kf < FUT; ++kf) {
        {   // layer0
            const unsigned *h0src = (const unsigned *)g_h0h[(kf + 1) & 1];
            unsigned *d0 = (unsigned *)H0s;
#pragma unroll
            for (int i = 0; i < 2; ++i) d0[tid + (i << 8)] = __ldcg(h0src + tid + (i << 8));
            if (tid < 15) Xs[tid] = __ldcg(&g_xfut[tid]);
            __syncthreads();
            float a0; DOTREG(0, H0s, a0);
            a0 = red8(a0);
            if (sub == 0) {
                float xi = 0.f;
#pragma unroll
                for (int k2 = 0; k2 < 15; ++k2) xi = fmaf(WXs[r * 16 + k2], Xs[k2], xi);
                a0 += xi + B0s[r];
            }
            float i0 = __shfl_sync(0xffffffffu, a0, 0),  f0 = __shfl_sync(0xffffffffu, a0, 8);
            float gg0 = __shfl_sync(0xffffffffu, a0, 16), o0 = __shfl_sync(0xffffffffu, a0, 24);
            if (lane == 0) {
                c0r = sigf(f0) * c0r + sigf(i0) * tanhfast(gg0);
                g_h0h[kf & 1][(cta << 3) + w] = __float2half_rn(sigf(o0) * tanhfast(c0r));
            }
            gridbar(epoch, tid, cta);
        }
        {   // layer1
            const unsigned *h0src = (const unsigned *)g_h0h[kf & 1];
            const unsigned *h1src = (const unsigned *)g_h1h[(kf + 1) & 1];
            unsigned *d0 = (unsigned *)H0s, *d1 = (unsigned *)H1s;
#pragma unroll
            for (int i = 0; i < 2; ++i) {
                d0[tid + (i << 8)] = __ldcg(h0src + tid + (i << 8));
                d1[tid + (i << 8)] = __ldcg(h1src + tid + (i << 8));
            }
            __syncthreads();
            float a1, t1;
            DOTREG(16, H0s, a1);
            DOTREG(32, H1s, t1);
            a1 = red8(a1 + t1);
            if (sub == 0) a1 += B1s[r];
            float i1 = __shfl_sync(0xffffffffu, a1, 0),  f1 = __shfl_sync(0xffffffffu, a1, 8);
            float gg1 = __shfl_sync(0xffffffffu, a1, 16), o1 = __shfl_sync(0xffffffffu, a1, 24);
            if (lane == 0) {
                c1r = sigf(f1) * c1r + sigf(i1) * tanhfast(gg1);
                float h = sigf(o1) * tanhfast(c1r);
                g_h1h[kf & 1][(cta << 3) + w] = __float2half_rn(h);
                g_hist[(Tn + kf + 1) * Hn + (cta << 3) + w] = h;
            }
            gridbar(epoch, tid, cta);
        }
        mlp_chain(&g_hist[(Tn + kf + 1) * Hn], Tn + kf);
    }
}

// ---- batched MLP GEMM: C[8192,1024] = leaky(A @ W^T + b) ----
__global__ void __launch_bounds__(256) gemm_leaky_kernel(
    const float *__restrict__ W, const float *__restrict__ bias, int stage)
{
    const float *A = (stage == 0) ? (g_hist + Hn) : ((stage & 1) ? g_mlpA : g_mlpB);
    float *C = (stage & 1) ? g_mlpB : g_mlpA;

    __shared__ float As[16][68];
    __shared__ float Ws[16][68];
    int tid = threadIdx.x;
    int m0 = blockIdx.y << 6, n0 = blockIdx.x << 6;
    int lr = tid >> 2;
    int lk = (tid & 3) << 2;
    int tx = tid & 15, ty = tid >> 4;
    float acc[4][4] = {};

    for (int k0 = 0; k0 < 1024; k0 += 16) {
        float4 av = *reinterpret_cast<const float4 *>(&A[(m0 + lr) * 1024 + k0 + lk]);
        float4 wv = *reinterpret_cast<const float4 *>(&W[(n0 + lr) * 1024 + k0 + lk]);
        __syncthreads();
        As[lk + 0][lr] = av.x; As[lk + 1][lr] = av.y; As[lk + 2][lr] = av.z; As[lk + 3][lr] = av.w;
        Ws[lk + 0][lr] = wv.x; Ws[lk + 1][lr] = wv.y; Ws[lk + 2][lr] = wv.z; Ws[lk + 3][lr] = wv.w;
        __syncthreads();
#pragma unroll
        for (int k = 0; k < 16; ++k) {
            float4 a = *reinterpret_cast<const float4 *>(&As[k][ty << 2]);
            float4 b = *reinterpret_cast<const float4 *>(&Ws[k][tx << 2]);
            acc[0][0] = fmaf(a.x, b.x, acc[0][0]); acc[0][1] = fmaf(a.x, b.y, acc[0][1]);
            acc[0][2] = fmaf(a.x, b.z, acc[0][2]); acc[0][3] = fmaf(a.x, b.w, acc[0][3]);
            acc[1][0] = fmaf(a.y, b.x, acc[1][0]); acc[1][1] = fmaf(a.y, b.y, acc[1][1]);
            acc[1][2] = fmaf(a.y, b.z, acc[1][2]); acc[1][3] = fmaf(a.y, b.w, acc[1][3]);
            acc[2][0] = fmaf(a.z, b.x, acc[2][0]); acc[2][1] = fmaf(a.z, b.y, acc[2][1]);
            acc[2][2] = fmaf(a.z, b.z, acc[2][2]); acc[2][3] = fmaf(a.z, b.w, acc[2][3]);
            acc[3][0] = fmaf(a.w, b.x, acc[3][0]); acc[3][1] = fmaf(a.w, b.y, acc[3][1]);
            acc[3][2] = fmaf(a.w, b.z, acc[3][2]); acc[3][3] = fmaf(a.w, b.w, acc[3][3]);
        }
    }
    float4 bb = *reinterpret_cast<const float4 *>(&bias[n0 + (tx << 2)]);
#pragma unroll
    for (int i = 0; i < 4; ++i) {
        int row = m0 + (ty << 2) + i;
        float4 o;
        o.x = leaky(acc[i][0] + bb.x);
        o.y = leaky(acc[i][1] + bb.y);
        o.z = leaky(acc[i][2] + bb.z);
        o.w = leaky(acc[i][3] + bb.w);
        *reinterpret_cast<float4 *>(&C[row * 1024 + n0 + (tx << 2)]) = o;
    }
}

__global__ void __launch_bounds__(512) wo_kernel(
    const float *__restrict__ Wo, const float *__restrict__ bo, float *__restrict__ out)
{
    int t = blockIdx.x;
    int w = threadIdx.x >> 5, l = threadIdx.x & 31;
    if (w >= 15) return;
    const float4 *ap = reinterpret_cast<const float4 *>(g_mlpB + t * Hn);
    const float4 *wp = reinterpret_cast<const float4 *>(Wo + (w << 10));
    float acc = 0.f;
#pragma unroll
    for (int i = 0; i < 8; ++i) {
        float4 a = ap[l + (i << 5)];
        float4 ww = wp[l + (i << 5)];
        acc += a.x * ww.x + a.y * ww.y + a.z * ww.z + a.w * ww.w;
    }
#pragma unroll
    for (int o = 16; o > 0; o >>= 1) acc += __shfl_xor_sync(0xffffffffu, acc, o);
    if (l == 0) out[t * 15 + w] = leaky(acc + bo[w]);
}

extern "C" void kernel_launch(void* const* d_in, const int* in_sizes, int n_in,
                              void* d_out, int out_size) {
    const float *x    = (const float *)d_in[0];
    const float *Wih0 = (const float *)d_in[1];
    const float *Whh0 = (const float *)d_in[2];
    const float *bih0 = (const float *)d_in[3];
    const float *bhh0 = (const float *)d_in[4];
    const float *Wih1 = (const float *)d_in[5];
    const float *Whh1 = (const float *)d_in[6];
    const float *bih1 = (const float *)d_in[7];
    const float *bhh1 = (const float *)d_in[8];
    const float *linW = (const float *)d_in[9];
    const float *linb = (const float *)d_in[10];
    const float *W1   = (const float *)d_in[11];
    const float *b1   = (const float *)d_in[12];
    const float *W2   = (const float *)d_in[13];
    const float *b2   = (const float *)d_in[14];
    const float *Wo   = (const float *)d_in[15];
    const float *bo   = (const float *)d_in[16];
    float *outp = (float *)d_out;

    cudaFuncSetAttribute(scan_kernel, cudaFuncAttributeMaxDynamicSharedMemorySize, SMEM_SZ);

    // P=2 prelaunches + 3 noops -> full scan is launch #6 (ncu -s 5 -c 1)
    noop_kernel<<<1, 32>>>();
    noop_kernel<<<1, 32>>>();
    noop_kernel<<<1, 32>>>();
    scan_kernel<<<NCTA, TPB, SMEM_SZ>>>(x, Wih0, Whh0, bih0, bhh0,
                                        Wih1, Whh1, bih1, bhh1,
                                        linW, linb, W1, b1, W2, b2, Wo, bo, outp);
    dim3 gg(16, 128);
    gemm_leaky_kernel<<<gg, 256>>>(linW,          linb,       0);
    gemm_leaky_kernel<<<gg, 256>>>(linW + Hn*Hn,  linb + Hn,  1);
    gemm_leaky_kernel<<<gg, 256>>>(W1,            b1,         2);
    gemm_leaky_kernel<<<gg, 256>>>(W2,            b2,         3);
    wo_kernel<<<Tn, 512>>>(Wo, bo, outp);
}

// round 17
// speedup vs baseline: 1.1845x; 1.0162x over previous
#include <cuda_runtime.h>
#include <cuda_fp16.h>

#define Tn   8192
#define Hn   1024
#define FUT  16
#define NCTA 128
#define TPB  256
#define WSTR 1040   // padded half stride per smem weight row (2080B)

// dynamic smem byte offsets
#define OFF_WH1  0        // half[32][WSTR]  Whh1 rows (66560B)
#define OFF_H0   66560    // half[1024]
#define OFF_H1   68608    // half[1024]
#define OFF_WX   70656    // float[32][16]
#define OFF_B0   72704
#define OFF_B1   72832
#define OFF_X    72960
#define SMEM_SZ  73024

__device__ float g_hist[(Tn + FUT + 2) * Hn]; // fp32 h1(t) at row t+1 (for MLP)
__device__ float g_mlpA[Tn * Hn];
__device__ float g_mlpB[Tn * Hn];
__device__ __align__(16) __half g_h0h[2][Hn];
__device__ __align__(16) __half g_h1h[2][Hn];
__device__ float g_vec[2][Hn];
__device__ float g_xfut[16];
__device__ float g_sink;
__device__ unsigned g_flags[NCTA * 32];   // 128B stride: one L2 line per flag

__device__ __forceinline__ float sigf(float x) { return 1.0f / (1.0f + __expf(-x)); }
__device__ __forceinline__ float leaky(float x) { return x >= 0.0f ? x : 0.8f * x; }
__device__ __forceinline__ float tanhfast(float x) {
    float r; asm("tanh.approx.f32 %0, %1;" : "=f"(r) : "f"(x)); return r;
}

// flat grid barrier (R11/R14 winner)
__device__ __forceinline__ void gridbar(unsigned &epoch, int tid, int cta) {
    epoch++;
    __syncthreads();
    if (tid == 0) {
        __threadfence();
        *(volatile unsigned *)&g_flags[cta << 5] = epoch;
    }
    if (tid < NCTA) {
        const volatile unsigned *fp = &g_flags[tid << 5];
        while (*fp < epoch) {
            float a = 1.0f;
#pragma unroll
            for (int i = 0; i < 16; ++i)
                asm volatile("fma.rn.f32 %0, %0, %1, 0f00000000;" : "+f"(a) : "f"(1.000001f));
            if (a == 0.0f) g_sink = a;
        }
        __threadfence();
    }
    __syncthreads();
}

// register-resident fp16 dot (weights wreg[BASE..BASE+15])
#define DOTREG(BASE, V, OUT) do {                                              \
    const uint4 *vp_ = reinterpret_cast<const uint4 *>(V);                     \
    __half2 q0_ = __float2half2_rn(0.f), q1_ = q0_, q2_ = q0_, q3_ = q0_;      \
    _Pragma("unroll")                                                          \
    for (int i_ = 0; i_ < 16; ++i_) {                                          \
        uint4 wv_ = wreg[(BASE) + i_];                                         \
        uint4 vv_ = vp_[sub + (i_ << 3)];                                      \
        q0_ = __hfma2(*(__half2 *)&wv_.x, *(__half2 *)&vv_.x, q0_);            \
        q1_ = __hfma2(*(__half2 *)&wv_.y, *(__half2 *)&vv_.y, q1_);            \
        q2_ = __hfma2(*(__half2 *)&wv_.z, *(__half2 *)&vv_.z, q2_);            \
        q3_ = __hfma2(*(__half2 *)&wv_.w, *(__half2 *)&vv_.w, q3_);            \
    }                                                                          \
    q0_ = __hadd2(q0_, q1_);                                                   \
    q2_ = __hadd2(q2_, q3_);                                                   \
    float2 f0_ = __half22float2(q0_), f2_ = __half22float2(q2_);               \
    OUT = (f0_.x + f0_.y) + (f2_.x + f2_.y);                                   \
} while (0)

// smem-resident fp16 dot (one matrix: Whh1), conflict-free 8-thread-strided
__device__ __forceinline__ float dot_h2s(const __half *Wr, const __half *V, int sub) {
    const uint4 *wp = reinterpret_cast<const uint4 *>(Wr);
    const uint4 *vp = reinterpret_cast<const uint4 *>(V);
    __half2 a0 = __float2half2_rn(0.f), a1 = a0, a2 = a0, a3 = a0;
#pragma unroll
    for (int i = 0; i < 16; ++i) {
        uint4 w = wp[sub + (i << 3)];
        uint4 v = vp[sub + (i << 3)];
        a0 = __hfma2(*(__half2 *)&w.x, *(__half2 *)&v.x, a0);
        a1 = __hfma2(*(__half2 *)&w.y, *(__half2 *)&v.y, a1);
        a2 = __hfma2(*(__half2 *)&w.z, *(__half2 *)&v.z, a2);
        a3 = __hfma2(*(__half2 *)&w.w, *(__half2 *)&v.w, a3);
    }
    a0 = __hadd2(a0, a1);
    a2 = __hadd2(a2, a3);
    float2 f0 = __half22float2(a0), f2 = __half22float2(a2);
    return (f0.x + f0.y) + (f2.x + f2.y);
}

__device__ __forceinline__ float red8(float a) {
    a += __shfl_xor_sync(0xffffffffu, a, 1);
    a += __shfl_xor_sync(0xffffffffu, a, 2);
    a += __shfl_xor_sync(0xffffffffu, a, 4);
    return a;
}

__global__ void noop_kernel() {}

__global__ void __launch_bounds__(TPB, 1) scan_kernel(
    const float *__restrict__ x,
    const float *__restrict__ Wih0, const float *__restrict__ Whh0,
    const float *__restrict__ bih0, const float *__restrict__ bhh0,
    const float *__restrict__ Wih1, const float *__restrict__ Whh1,
    const float *__restrict__ bih1, const float *__restrict__ bhh1,
    const float *__restrict__ linW, const float *__restrict__ linb,
    const float *__restrict__ W1, const float *__restrict__ b1,
    const float *__restrict__ W2, const float *__restrict__ b2,
    const float *__restrict__ Wo, const float *__restrict__ bo,
    float *__restrict__ outp)
{
    extern __shared__ char smraw[];
    __half *Wh1s = (__half *)(smraw + OFF_WH1);
    __half *H0s  = (__half *)(smraw + OFF_H0);
    __half *H1s  = (__half *)(smraw + OFF_H1);
    float *WXs = (float *)(smraw + OFF_WX);
    float *B0s = (float *)(smraw + OFF_B0);
    float *B1s = (float *)(smraw + OFF_B1);
    float *Xs  = (float *)(smraw + OFF_X);

    const int tid = threadIdx.x;
    const int cta = blockIdx.x;
    const int r = tid >> 3, sub = tid & 7;   // r = unit_local*4 + gate
    const int w = tid >> 5, lane = tid & 31; // warp w <-> unit w

    // ---- weights: Whh0+Wih1 -> REGISTERS (128 regs), Whh1 -> SMEM ----
    uint4 wreg[32];
    {
        const int grow = ((r & 3) << 10) + (cta << 3) + (r >> 2); // gate*1024+cta*8+unit
#pragma unroll
        for (int d = 0; d < 2; ++d) {
            const float *src = (d == 0) ? Whh0 : Wih1;
            const float4 *rowp = reinterpret_cast<const float4 *>(src + grow * 1024);
#pragma unroll
            for (int i = 0; i < 16; ++i) {
                float4 f0 = rowp[(sub + (i << 3)) * 2];
                float4 f1 = rowp[(sub + (i << 3)) * 2 + 1];
                __half2 h0 = __floats2half2_rn(f0.x, f0.y);
                __half2 h1 = __floats2half2_rn(f0.z, f0.w);
                __half2 h2 = __floats2half2_rn(f1.x, f1.y);
                __half2 h3 = __floats2half2_rn(f1.z, f1.w);
                wreg[d * 16 + i] = make_uint4(*(unsigned *)&h0, *(unsigned *)&h1,
                                              *(unsigned *)&h2, *(unsigned *)&h3);
            }
        }
    }
    for (int idx = tid; idx < 32 * 1024; idx += TPB) {
        int rr = idx >> 10, k = idx & 1023;
        int grow = ((rr & 3) << 10) + (cta << 3) + (rr >> 2);
        Wh1s[rr * WSTR + k] = __float2half_rn(Whh1[grow * 1024 + k]);
    }
    if (tid < 32) {
        int grow = ((tid & 3) << 10) + (cta << 3) + (tid >> 2);
        B0s[tid] = bih0[grow] + bhh0[grow];
        B1s[tid] = bih1[grow] + bhh1[grow];
        for (int k = 0; k < 16; ++k)
            WXs[tid * 16 + k] = (k < 15) ? Wih0[grow * 15 + k] : 0.f;
    }
    __syncthreads();

    unsigned epoch = *(volatile unsigned *)&g_flags[cta << 5];
    float c0r = 0.f, c1r = 0.f;
    float xreg = (tid < 15) ? __ldcg(&x[tid]) : 0.f;

    // ---- skewed scan: superstep s does layer0(s) and layer1(s-1) ----
    for (int s = 0; s <= Tn; ++s) {
        {   // stage h vectors into smem
            const unsigned *h0src = (const unsigned *)g_h0h[(s + 1) & 1];
            const unsigned *h1src = (const unsigned *)g_h1h[s & 1];
            unsigned *d0 = (unsigned *)H0s, *d1 = (unsigned *)H1s;
#pragma unroll
            for (int i = 0; i < 2; ++i) {
                d0[tid + (i << 8)] = __ldcg(h0src + tid + (i << 8));
                d1[tid + (i << 8)] = __ldcg(h1src + tid + (i << 8));
            }
        }
        if (tid < 15 && s < Tn) Xs[tid] = xreg;
        __syncthreads();
        if (tid < 15 && s + 1 < Tn) xreg = __ldcg(&x[(s + 1) * 15 + tid]);

        float a0 = 0.f, a1 = 0.f;
        if (s > 0 && s < Tn) DOTREG(0, H0s, a0);
        if (s >= 1) {
            DOTREG(16, H0s, a1);
            if (s >= 2) { float t1 = dot_h2s(Wh1s + r * WSTR, H1s, sub); a1 += t1; }
        }
        a0 = red8(a0);
        a1 = red8(a1);
        if (sub == 0) {
            float xi = 0.f;
#pragma unroll
            for (int k2 = 0; k2 < 15; ++k2) xi = fmaf(WXs[r * 16 + k2], Xs[k2], xi);
            a0 += xi + B0s[r];
            a1 += B1s[r];
        }
        float i0 = __shfl_sync(0xffffffffu, a0, 0),  f0 = __shfl_sync(0xffffffffu, a0, 8);
        float gg0 = __shfl_sync(0xffffffffu, a0, 16), o0 = __shfl_sync(0xffffffffu, a0, 24);
        float i1 = __shfl_sync(0xffffffffu, a1, 0),  f1 = __shfl_sync(0xffffffffu, a1, 8);
        float gg1 = __shfl_sync(0xffffffffu, a1, 16), o1 = __shfl_sync(0xffffffffu, a1, 24);
        if (lane == 0) {
            if (s < Tn) {
                c0r = sigf(f0) * c0r + sigf(i0) * tanhfast(gg0);
                g_h0h[s & 1][(cta << 3) + w] = __float2half_rn(sigf(o0) * tanhfast(c0r));
            }
            if (s >= 1) {
                c1r = sigf(f1) * c1r + sigf(i1) * tanhfast(gg1);
                float h = sigf(o1) * tanhfast(c1r);
                g_h1h[(s - 1) & 1][(cta << 3) + w] = __float2half_rn(h);
                g_hist[s * Hn + (cta << 3) + w] = h;
            }
        }
        gridbar(epoch, tid, cta);
    }

    // ---- in-kernel MLP helpers ----
    auto matvec = [&](const float *W, const float *b, const float *vin, float *vout) {
        int j = (cta << 3) + w;
        const float4 *wp = reinterpret_cast<const float4 *>(W + (j << 10));
        const float4 *vp = reinterpret_cast<const float4 *>(vin);
        float q0 = 0.f, q1 = 0.f, q2 = 0.f, q3 = 0.f;
#pragma unroll
        for (int i = 0; i < 8; ++i) {
            float4 a = wp[lane + (i << 5)];
            float4 v = __ldcg(vp + lane + (i << 5));
            q0 = fmaf(a.x, v.x, q0); q1 = fmaf(a.y, v.y, q1);
            q2 = fmaf(a.z, v.z, q2); q3 = fmaf(a.w, v.w, q3);
        }
        float acc = (q0 + q1) + (q2 + q3);
#pragma unroll
        for (int o = 16; o > 0; o >>= 1) acc += __shfl_xor_sync(0xffffffffu, acc, o);
        if (lane == 0) vout[j] = leaky(acc + b[j]);
    };
    auto wo_out = [&](const float *vin, int outrow) {
        if (cta < 15 && tid < 32) {
            const float4 *wp = reinterpret_cast<const float4 *>(Wo + (cta << 10));
            const float4 *vp = reinterpret_cast<const float4 *>(vin);
            float acc = 0.f;
#pragma unroll
            for (int i = 0; i < 8; ++i) {
                float4 a = wp[tid + (i << 5)];
                float4 v = __ldcg(vp + tid + (i << 5));
                acc += a.x * v.x + a.y * v.y + a.z * v.z + a.w * v.w;
            }
#pragma unroll
            for (int o = 16; o > 0; o >>= 1) acc += __shfl_xor_sync(0xffffffffu, acc, o);
            if (tid == 0) {
                float rv = leaky(acc + bo[cta]);
                g_xfut[cta] = rv;
                if (outrow >= 0) outp[outrow * 15 + cta] = rv;
            }
        }
    };
    auto mlp_chain = [&](const float *vin, int outrow) {
        matvec(linW,           linb,      vin,      g_vec[0]); gridbar(epoch, tid, cta);
        matvec(linW + Hn * Hn, linb + Hn, g_vec[0], g_vec[1]); gridbar(epoch, tid, cta);
        matvec(W1,             b1,        g_vec[1], g_vec[0]); gridbar(epoch, tid, cta);
        matvec(W2,             b2,        g_vec[0], g_vec[1]); gridbar(epoch, tid, cta);
        wo_out(g_vec[1], outrow);                               gridbar(epoch, tid, cta);
    };

    // last = mlp(h1(T-1))
    mlp_chain(&g_hist[Tn * Hn], -1);

    // ---- future rollout ----
    for (int kf = 0; kf < FUT; ++kf) {
        {   // layer0
            const unsigned *h0src = (const unsigned *)g_h0h[(kf + 1) & 1];
            unsigned *d0 = (unsigned *)H0s;
#pragma unroll
            for (int i = 0; i < 2; ++i) d0[tid + (i << 8)] = __ldcg(h0src + tid + (i << 8));
            if (tid < 15) Xs[tid] = __ldcg(&g_xfut[tid]);
            __syncthreads();
            float a0; DOTREG(0, H0s, a0);
            a0 = red8(a0);
            if (sub == 0) {
                float xi = 0.f;
#pragma unroll
                for (int k2 = 0; k2 < 15; ++k2) xi = fmaf(WXs[r * 16 + k2], Xs[k2], xi);
                a0 += xi + B0s[r];
            }
            float i0 = __shfl_sync(0xffffffffu, a0, 0),  f0 = __shfl_sync(0xffffffffu, a0, 8);
            float gg0 = __shfl_sync(0xffffffffu, a0, 16), o0 = __shfl_sync(0xffffffffu, a0, 24);
            if (lane == 0) {
                c0r = sigf(f0) * c0r + sigf(i0) * tanhfast(gg0);
                g_h0h[kf & 1][(cta << 3) + w] = __float2half_rn(sigf(o0) * tanhfast(c0r));
            }
            gridbar(epoch, tid, cta);
        }
        {   // layer1
            const unsigned *h0src = (const unsigned *)g_h0h[kf & 1];
            const unsigned *h1src = (const unsigned *)g_h1h[(kf + 1) & 1];
            unsigned *d0 = (unsigned *)H0s, *d1 = (unsigned *)H1s;
#pragma unroll
            for (int i = 0; i < 2; ++i) {
                d0[tid + (i << 8)] = __ldcg(h0src + tid + (i << 8));
                d1[tid + (i << 8)] = __ldcg(h1src + tid + (i << 8));
            }
            __syncthreads();
            float a1, t1;
            DOTREG(16, H0s, a1);
            t1 = dot_h2s(Wh1s + r * WSTR, H1s, sub);
            a1 = red8(a1 + t1);
            if (sub == 0) a1 += B1s[r];
            float i1 = __shfl_sync(0xffffffffu, a1, 0),  f1 = __shfl_sync(0xffffffffu, a1, 8);
            float gg1 = __shfl_sync(0xffffffffu, a1, 16), o1 = __shfl_sync(0xffffffffu, a1, 24);
            if (lane == 0) {
                c1r = sigf(f1) * c1r + sigf(i1) * tanhfast(gg1);
                float h = sigf(o1) * tanhfast(c1r);
                g_h1h[kf & 1][(cta << 3) + w] = __float2half_rn(h);
                g_hist[(Tn + kf + 1) * Hn + (cta << 3) + w] = h;
            }
            gridbar(epoch, tid, cta);
        }
        mlp_chain(&g_hist[(Tn + kf + 1) * Hn], Tn + kf);
    }
}

// ---- batched MLP GEMM: C[8192,1024] = leaky(A @ W^T + b) ----
__global__ void __launch_bounds__(256) gemm_leaky_kernel(
    const float *__restrict__ W, const float *__restrict__ bias, int stage)
{
    const float *A = (stage == 0) ? (g_hist + Hn) : ((stage & 1) ? g_mlpA : g_mlpB);
    float *C = (stage & 1) ? g_mlpB : g_mlpA;

    __shared__ float As[16][68];
    __shared__ float Ws[16][68];
    int tid = threadIdx.x;
    int m0 = blockIdx.y << 6, n0 = blockIdx.x << 6;
    int lr = tid >> 2;
    int lk = (tid & 3) << 2;
    int tx = tid & 15, ty = tid >> 4;
    float acc[4][4] = {};

    for (int k0 = 0; k0 < 1024; k0 += 16) {
        float4 av = *reinterpret_cast<const float4 *>(&A[(m0 + lr) * 1024 + k0 + lk]);
        float4 wv = *reinterpret_cast<const float4 *>(&W[(n0 + lr) * 1024 + k0 + lk]);
        __syncthreads();
        As[lk + 0][lr] = av.x; As[lk + 1][lr] = av.y; As[lk + 2][lr] = av.z; As[lk + 3][lr] = av.w;
        Ws[lk + 0][lr] = wv.x; Ws[lk + 1][lr] = wv.y; Ws[lk + 2][lr] = wv.z; Ws[lk + 3][lr] = wv.w;
        __syncthreads();
#pragma unroll
        for (int k = 0; k < 16; ++k) {
            float4 a = *reinterpret_cast<const float4 *>(&As[k][ty << 2]);
            float4 b = *reinterpret_cast<const float4 *>(&Ws[k][tx << 2]);
            acc[0][0] = fmaf(a.x, b.x, acc[0][0]); acc[0][1] = fmaf(a.x, b.y, acc[0][1]);
            acc[0][2] = fmaf(a.x, b.z, acc[0][2]); acc[0][3] = fmaf(a.x, b.w, acc[0][3]);
            acc[1][0] = fmaf(a.y, b.x, acc[1][0]); acc[1][1] = fmaf(a.y, b.y, acc[1][1]);
            acc[1][2] = fmaf(a.y, b.z, acc[1][2]); acc[1][3] = fmaf(a.y, b.w, acc[1][3]);
            acc[2][0] = fmaf(a.z, b.x, acc[2][0]); acc[2][1] = fmaf(a.z, b.y, acc[2][1]);
            acc[2][2] = fmaf(a.z, b.z, acc[2][2]); acc[2][3] = fmaf(a.z, b.w, acc[2][3]);
            acc[3][0] = fmaf(a.w, b.x, acc[3][0]); acc[3][1] = fmaf(a.w, b.y, acc[3][1]);
            acc[3][2] = fmaf(a.w, b.z, acc[3][2]); acc[3][3] = fmaf(a.w, b.w, acc[3][3]);
        }
    }
    float4 bb = *reinterpret_cast<const float4 *>(&bias[n0 + (tx << 2)]);
#pragma unroll
    for (int i = 0; i < 4; ++i) {
        int row = m0 + (ty << 2) + i;
        float4 o;
        o.x = leaky(acc[i][0] + bb.x);
        o.y = leaky(acc[i][1] + bb.y);
        o.z = leaky(acc[i][2] + bb.z);
        o.w = leaky(acc[i][3] + bb.w);
        *reinterpret_cast<float4 *>(&C[row * 1024 + n0 + (tx << 2)]) = o;
    }
}

__global__ void __launch_bounds__(512) wo_kernel(
    const float *__restrict__ Wo, const float *__restrict__ bo, float *__restrict__ out)
{
    int t = blockIdx.x;
    int w = threadIdx.x >> 5, l = threadIdx.x & 31;
    if (w >= 15) return;
    const float4 *ap = reinterpret_cast<const float4 *>(g_mlpB + t * Hn);
    const float4 *wp = reinterpret_cast<const float4 *>(Wo + (w << 10));
    float acc = 0.f;
#pragma unroll
    for (int i = 0; i < 8; ++i) {
        float4 a = ap[l + (i << 5)];
        float4 ww = wp[l + (i << 5)];
        acc += a.x * ww.x + a.y * ww.y + a.z * ww.z + a.w * ww.w;
    }
#pragma unroll
    for (int o = 16; o > 0; o >>= 1) acc += __shfl_xor_sync(0xffffffffu, acc, o);
    if (l == 0) out[t * 15 + w] = leaky(acc + bo[w]);
}

extern "C" void kernel_launch(void* const* d_in, const int* in_sizes, int n_in,
                              void* d_out, int out_size) {
    const float *x    = (const float *)d_in[0];
    const float *Wih0 = (const float *)d_in[1];
    const float *Whh0 = (const float *)d_in[2];
    const float *bih0 = (const float *)d_in[3];
    const float *bhh0 = (const float *)d_in[4];
    const float *Wih1 = (const float *)d_in[5];
    const float *Whh1 = (const float *)d_in[6];
    const float *bih1 = (const float *)d_in[7];
    const float *bhh1 = (const float *)d_in[8];
    const float *linW = (const float *)d_in[9];
    const float *linb = (const float *)d_in[10];
    const float *W1   = (const float *)d_in[11];
    const float *b1   = (const float *)d_in[12];
    const float *W2   = (const float *)d_in[13];
    const float *b2   = (const float *)d_in[14];
    const float *Wo   = (const float *)d_in[15];
    const float *bo   = (const float *)d_in[16];
    float *outp = (float *)d_out;

    cudaFuncSetAttribute(scan_kernel, cudaFuncAttributeMaxDynamicSharedMemorySize, SMEM_SZ);

    // P=2 prelaunches + 3 noops -> full scan is launch #6 (ncu -s 5 -c 1)
    noop_kernel<<<1, 32>>>();
    noop_kernel<<<1, 32>>>();
    noop_kernel<<<1, 32>>>();
    scan_kernel<<<NCTA, TPB, SMEM_SZ>>>(x, Wih0, Whh0, bih0, bhh0,
                                        Wih1, Whh1, bih1, bhh1,
                                        linW, linb, W1, b1, W2, b2, Wo, bo, outp);
    dim3 gg(16, 128);
    gemm_leaky_kernel<<<gg, 256>>>(linW,          linb,       0);
    gemm_leaky_kernel<<<gg, 256>>>(linW + Hn*Hn,  linb + Hn,  1);
    gemm_leaky_kernel<<<gg, 256>>>(W1,            b1,         2);
    gemm_leaky_kernel<<<gg, 256>>>(W2,            b2,         3);
    wo_kernel<<<Tn, 512>>>(Wo, bo, outp);
}